// round 4
// baseline (speedup 1.0000x reference)
#include <cuda_runtime.h>
#include <math.h>
#include <stdint.h>

#define N_NODES 25000
#define N_EDGES 400000
#define EMBED   128
#define NHEADS  8
#define DKH     16
#define TILE_N  64

// ---------------- scratch (static device globals; no allocation) -----------
__device__ __align__(16) float g_Q[N_NODES * EMBED];
__device__ __align__(16) float g_K[N_NODES * EMBED];
__device__ __align__(16) float g_V[N_NODES * EMBED];
__device__ __align__(16) float g_agg[N_NODES * EMBED];   // unnormalized sum(e * v)
__device__ float g_z[N_NODES * NHEADS];                  // sum of exp (unshifted)
__device__ int   g_cnt[N_NODES];                         // edges per dst
__device__ int   g_start[N_NODES];                       // exclusive prefix
__device__ int   g_cur[N_NODES];                         // scatter cursor
__device__ int   g_se[N_EDGES];                          // edge ids sorted by dst

// ---------------- K0: init (counters only) --------------------------------
__global__ void init_kernel() {
    int i = blockIdx.x * blockDim.x + threadIdx.x;
    if (i < N_NODES) g_cnt[i] = 0;
}

// ---------------- sort by dst: hist -> scan -> scatter ---------------------
__global__ void hist_kernel(const int* __restrict__ ei) {
    int e = blockIdx.x * blockDim.x + threadIdx.x;
    if (e < N_EDGES) atomicAdd(&g_cnt[ei[e]], 1);
}

__global__ void scan_kernel() {   // single block, 1024 threads
    __shared__ int s[1024];
    int t = threadIdx.x;
    const int CH = (N_NODES + 1023) / 1024;   // 25
    int b0 = t * CH;
    int sum = 0;
    for (int i = 0; i < CH; ++i) {
        int idx = b0 + i;
        if (idx < N_NODES) sum += g_cnt[idx];
    }
    s[t] = sum;
    __syncthreads();
    for (int off = 1; off < 1024; off <<= 1) {
        int v = (t >= off) ? s[t - off] : 0;
        __syncthreads();
        s[t] += v;
        __syncthreads();
    }
    int excl = (t == 0) ? 0 : s[t - 1];
    for (int i = 0; i < CH; ++i) {
        int idx = b0 + i;
        if (idx < N_NODES) {
            g_start[idx] = excl;
            g_cur[idx]   = excl;
            excl += g_cnt[idx];
        }
    }
}

__global__ void scatter_kernel(const int* __restrict__ ei) {
    int e = blockIdx.x * blockDim.x + threadIdx.x;
    if (e < N_EDGES) {
        int dst = ei[e];
        int pos = atomicAdd(&g_cur[dst], 1);
        g_se[pos] = e;
    }
}

// ============ tiled GEMM helpers ==========================================
#define XN (TILE_N + 4)
#define WJ (EMBED + 4)

__device__ __forceinline__ void load_w_T(float* ws, const float* __restrict__ W, int tid) {
#pragma unroll
    for (int r = 0; r < 16; ++r) {
        int idx = r * 256 + tid;
        int j   = idx >> 5;
        int d4  = idx & 31;
        float4 w = ((const float4*)(W + j * EMBED))[d4];
        int d = d4 * 4;
        ws[(d + 0) * WJ + j] = w.x;
        ws[(d + 1) * WJ + j] = w.y;
        ws[(d + 2) * WJ + j] = w.z;
        ws[(d + 3) * WJ + j] = w.w;
    }
}

__device__ __forceinline__ void gemm_tile(const float* xs, const float* ws,
                                          int tn, int tj, float acc[4][8],
                                          const float* __restrict__ bias) {
    int jb = tj * 8;
#pragma unroll
    for (int jj = 0; jj < 8; ++jj) {
        float b = bias[jb + jj];
#pragma unroll
        for (int i = 0; i < 4; ++i) acc[i][jj] = b;
    }
#pragma unroll 4
    for (int d = 0; d < EMBED; ++d) {
        float4 xv = *(const float4*)(xs + d * XN + tn * 4);
        float4 wa = *(const float4*)(ws + d * WJ + jb);
        float4 wb = *(const float4*)(ws + d * WJ + jb + 4);
        float xr[4] = {xv.x, xv.y, xv.z, xv.w};
        float wr[8] = {wa.x, wa.y, wa.z, wa.w, wb.x, wb.y, wb.z, wb.w};
#pragma unroll
        for (int i = 0; i < 4; ++i)
#pragma unroll
            for (int jj = 0; jj < 8; ++jj)
                acc[i][jj] += xr[i] * wr[jj];
    }
}

__device__ __forceinline__ void store_tile(float* dst, int n0, int tn, int tj,
                                           float acc[4][8]) {
    int jb = tj * 8;
#pragma unroll
    for (int i = 0; i < 4; ++i) {
        int n = n0 + tn * 4 + i;
        if (n < N_NODES) {
            float4* p = (float4*)(dst + n * EMBED + jb);
            p[0] = make_float4(acc[i][0], acc[i][1], acc[i][2], acc[i][3]);
            p[1] = make_float4(acc[i][4], acc[i][5], acc[i][6], acc[i][7]);
        }
    }
}

// ---------------- K1: Q/K/V projections (tiled) ---------------------------
__global__ __launch_bounds__(256, 2)
void qkv_kernel(const float* __restrict__ x,
                const float* __restrict__ Wq, const float* __restrict__ bq,
                const float* __restrict__ Wk, const float* __restrict__ bk,
                const float* __restrict__ Wv, const float* __restrict__ bv) {
    __shared__ float xs[EMBED * XN];
    __shared__ float ws[EMBED * WJ];
    int tid = threadIdx.x;
    int n0 = blockIdx.x * TILE_N;

#pragma unroll
    for (int r = 0; r < 8; ++r) {
        int idx = r * 256 + tid;
        int n  = idx >> 5;
        int d4 = idx & 31;
        float4 xv = (n0 + n < N_NODES)
                  ? ((const float4*)(x + (size_t)(n0 + n) * EMBED))[d4]
                  : make_float4(0.f, 0.f, 0.f, 0.f);
        int d = d4 * 4;
        xs[(d + 0) * XN + n] = xv.x;
        xs[(d + 1) * XN + n] = xv.y;
        xs[(d + 2) * XN + n] = xv.z;
        xs[(d + 3) * XN + n] = xv.w;
    }

    int tn = tid & 15;
    int tj = tid >> 4;
    float acc[4][8];

    load_w_T(ws, Wq, tid);
    __syncthreads();
    gemm_tile(xs, ws, tn, tj, acc, bq);
    __syncthreads();
    store_tile(g_Q, n0, tn, tj, acc);

    load_w_T(ws, Wk, tid);
    __syncthreads();
    gemm_tile(xs, ws, tn, tj, acc, bk);
    __syncthreads();
    store_tile(g_K, n0, tn, tj, acc);

    load_w_T(ws, Wv, tid);
    __syncthreads();
    gemm_tile(xs, ws, tn, tj, acc, bv);
    store_tile(g_V, n0, tn, tj, acc);
}

// ---------------- K2: per-node gather + softmax-accumulate (atomic-free) ---
// One warp per dst node. lane = eg*8 + h : eg in [0,4) edge slot, h head.
// Softmax is shift-invariant; logits are O(8), so no max-subtraction needed.
__global__ __launch_bounds__(256)
void gather_kernel(const int* __restrict__ ei,
                   const float* __restrict__ bias,
                   float* __restrict__ out_logits) {
    int warp = (blockIdx.x * blockDim.x + threadIdx.x) >> 5;
    if (warp >= N_NODES) return;
    int lane = threadIdx.x & 31;
    int h  = lane & 7;
    int eg = lane >> 3;
    int n = warp;

    const float4* qp = (const float4*)(g_Q + n * EMBED + h * DKH);
    float4 q0 = qp[0], q1 = qp[1], q2 = qp[2], q3 = qp[3];

    float accv[16];
#pragma unroll
    for (int j = 0; j < 16; ++j) accv[j] = 0.0f;
    float accz = 0.0f;

    int cnt  = g_cnt[n];
    int base = g_start[n];

    for (int i = eg; i < cnt; i += 4) {
        int eid = g_se[base + i];
        int src = ei[N_EDGES + eid];

        const float4* kp = (const float4*)(g_K + src * EMBED + h * DKH);
        float4 k0 = kp[0], k1 = kp[1], k2 = kp[2], k3 = kp[3];
        float dot = q0.x*k0.x + q0.y*k0.y + q0.z*k0.z + q0.w*k0.w
                  + q1.x*k1.x + q1.y*k1.y + q1.z*k1.z + q1.w*k1.w
                  + q2.x*k2.x + q2.y*k2.y + q2.z*k2.z + q2.w*k2.w
                  + q3.x*k3.x + q3.y*k3.y + q3.z*k3.z + q3.w*k3.w;
        float logit = 0.25f * dot + bias[eid * NHEADS + h];
        out_logits[eid * NHEADS + h] = logit;

        float ev = __expf(logit);
        accz += ev;

        const float4* vp = (const float4*)(g_V + src * EMBED + h * DKH);
        float4 v0 = vp[0], v1 = vp[1], v2 = vp[2], v3 = vp[3];
        accv[0]  += ev * v0.x;  accv[1]  += ev * v0.y;
        accv[2]  += ev * v0.z;  accv[3]  += ev * v0.w;
        accv[4]  += ev * v1.x;  accv[5]  += ev * v1.y;
        accv[6]  += ev * v1.z;  accv[7]  += ev * v1.w;
        accv[8]  += ev * v2.x;  accv[9]  += ev * v2.y;
        accv[10] += ev * v2.z;  accv[11] += ev * v2.w;
        accv[12] += ev * v3.x;  accv[13] += ev * v3.y;
        accv[14] += ev * v3.z;  accv[15] += ev * v3.w;
    }

    // reduce over the 4 edge-slot lanes sharing each head (xor 8, 16)
    accz += __shfl_xor_sync(0xffffffffu, accz, 8);
    accz += __shfl_xor_sync(0xffffffffu, accz, 16);
#pragma unroll
    for (int j = 0; j < 16; ++j) {
        accv[j] += __shfl_xor_sync(0xffffffffu, accv[j], 8);
        accv[j] += __shfl_xor_sync(0xffffffffu, accv[j], 16);
    }

    if (eg == 0) g_z[n * NHEADS + h] = accz;
    float4 w = make_float4(accv[eg * 4 + 0], accv[eg * 4 + 1],
                           accv[eg * 4 + 2], accv[eg * 4 + 3]);
    *(float4*)(g_agg + n * EMBED + h * DKH + eg * 4) = w;
}

// ---------------- K3: normalize + output projection (tiled) ---------------
__global__ __launch_bounds__(256, 2)
void out_kernel(const float* __restrict__ Wo,
                const float* __restrict__ bo,
                float* __restrict__ out) {
    __shared__ float xs[EMBED * XN];
    __shared__ float ws[EMBED * WJ];
    int tid = threadIdx.x;
    int n0 = blockIdx.x * TILE_N;

#pragma unroll
    for (int r = 0; r < 8; ++r) {
        int idx = r * 256 + tid;
        int n  = idx >> 5;
        int d4 = idx & 31;
        float4 xv = make_float4(0.f, 0.f, 0.f, 0.f);
        if (n0 + n < N_NODES) {
            int node = n0 + n;
            xv = ((const float4*)(g_agg + (size_t)node * EMBED))[d4];
            float z = g_z[node * NHEADS + (d4 >> 2)];
            float inv = (z > 0.0f) ? (1.0f / z) : 0.0f;
            xv.x *= inv; xv.y *= inv; xv.z *= inv; xv.w *= inv;
        }
        int d = d4 * 4;
        xs[(d + 0) * XN + n] = xv.x;
        xs[(d + 1) * XN + n] = xv.y;
        xs[(d + 2) * XN + n] = xv.z;
        xs[(d + 3) * XN + n] = xv.w;
    }

    load_w_T(ws, Wo, tid);
    __syncthreads();

    int tn = tid & 15;
    int tj = tid >> 4;
    float acc[4][8];
    gemm_tile(xs, ws, tn, tj, acc, bo);
    store_tile(out, n0, tn, tj, acc);
}

// ---------------- launch --------------------------------------------------
extern "C" void kernel_launch(void* const* d_in, const int* in_sizes, int n_in,
                              void* d_out, int out_size) {
    const float* x    = (const float*)d_in[0];
    const int*   ei   = (const int*)d_in[1];
    const float* bias = (const float*)d_in[2];
    const float* Wq   = (const float*)d_in[3];
    const float* bq   = (const float*)d_in[4];
    const float* Wk   = (const float*)d_in[5];
    const float* bk   = (const float*)d_in[6];
    const float* Wv   = (const float*)d_in[7];
    const float* bv   = (const float*)d_in[8];
    const float* Wo   = (const float*)d_in[9];
    const float* bo   = (const float*)d_in[10];

    float* out        = (float*)d_out;                       // [N_NODES, 128]
    float* out_logits = (float*)d_out + N_NODES * EMBED;     // [E, H, 1]

    init_kernel<<<(N_NODES + 255) / 256, 256>>>();
    hist_kernel<<<(N_EDGES + 255) / 256, 256>>>(ei);
    scan_kernel<<<1, 1024>>>();
    scatter_kernel<<<(N_EDGES + 255) / 256, 256>>>(ei);

    int nblk = (N_NODES + TILE_N - 1) / TILE_N;
    qkv_kernel<<<nblk, 256>>>(x, Wq, bq, Wk, bk, Wv, bv);

    int nwarp_blocks = (N_NODES * 32 + 255) / 256;
    gather_kernel<<<nwarp_blocks, 256>>>(ei, bias, out_logits);

    out_kernel<<<nblk, 256>>>(Wo, bo, out);
}

// round 5
// speedup vs baseline: 1.0152x; 1.0152x over previous
#include <cuda_runtime.h>
#include <math.h>
#include <stdint.h>

#define N_NODES 25000
#define N_EDGES 400000
#define EMBED   128
#define NHEADS  8
#define DKH     16
#define TILE_N  64

// ---------------- scratch (static device globals; no allocation) -----------
__device__ __align__(16) float g_Q[N_NODES * EMBED];
__device__ __align__(16) float g_K[N_NODES * EMBED];
__device__ __align__(16) float g_V[N_NODES * EMBED];
__device__ __align__(16) float g_agg[N_NODES * EMBED];   // normalized sum(e*v)/z
__device__ int   g_cnt[N_NODES];                         // edges per dst
__device__ int   g_start[N_NODES];                       // exclusive prefix
__device__ int   g_cur[N_NODES];                         // scatter cursor
__device__ __align__(8) int2 g_sedge[N_EDGES];           // (eid, src) sorted by dst

// ---------------- K0: init (counters only) --------------------------------
__global__ void init_kernel() {
    int i = blockIdx.x * blockDim.x + threadIdx.x;
    if (i < N_NODES) g_cnt[i] = 0;
}

// ---------------- sort by dst: hist -> scan -> scatter ---------------------
__global__ void hist_kernel(const int* __restrict__ ei) {
    int e = blockIdx.x * blockDim.x + threadIdx.x;
    if (e < N_EDGES) atomicAdd(&g_cnt[ei[e]], 1);
}

__global__ void scan_kernel() {   // single block, 1024 threads
    __shared__ int s[1024];
    int t = threadIdx.x;
    const int CH = (N_NODES + 1023) / 1024;   // 25
    int b0 = t * CH;
    int sum = 0;
    for (int i = 0; i < CH; ++i) {
        int idx = b0 + i;
        if (idx < N_NODES) sum += g_cnt[idx];
    }
    s[t] = sum;
    __syncthreads();
    for (int off = 1; off < 1024; off <<= 1) {
        int v = (t >= off) ? s[t - off] : 0;
        __syncthreads();
        s[t] += v;
        __syncthreads();
    }
    int excl = (t == 0) ? 0 : s[t - 1];
    for (int i = 0; i < CH; ++i) {
        int idx = b0 + i;
        if (idx < N_NODES) {
            g_start[idx] = excl;
            g_cur[idx]   = excl;
            excl += g_cnt[idx];
        }
    }
}

__global__ void scatter_kernel(const int* __restrict__ ei) {
    int e = blockIdx.x * blockDim.x + threadIdx.x;
    if (e < N_EDGES) {
        int dst = ei[e];
        int src = ei[N_EDGES + e];
        int pos = atomicAdd(&g_cur[dst], 1);
        g_sedge[pos] = make_int2(e, src);
    }
}

// ============ tiled GEMM helpers ==========================================
#define XN (TILE_N + 4)
#define WJ (EMBED + 4)

__device__ __forceinline__ void load_w_T(float* ws, const float* __restrict__ W, int tid) {
#pragma unroll
    for (int r = 0; r < 16; ++r) {
        int idx = r * 256 + tid;
        int j   = idx >> 5;
        int d4  = idx & 31;
        float4 w = ((const float4*)(W + j * EMBED))[d4];
        int d = d4 * 4;
        ws[(d + 0) * WJ + j] = w.x;
        ws[(d + 1) * WJ + j] = w.y;
        ws[(d + 2) * WJ + j] = w.z;
        ws[(d + 3) * WJ + j] = w.w;
    }
}

__device__ __forceinline__ void gemm_tile(const float* xs, const float* ws,
                                          int tn, int tj, float acc[4][8],
                                          const float* __restrict__ bias) {
    int jb = tj * 8;
#pragma unroll
    for (int jj = 0; jj < 8; ++jj) {
        float b = bias[jb + jj];
#pragma unroll
        for (int i = 0; i < 4; ++i) acc[i][jj] = b;
    }
#pragma unroll 4
    for (int d = 0; d < EMBED; ++d) {
        float4 xv = *(const float4*)(xs + d * XN + tn * 4);
        float4 wa = *(const float4*)(ws + d * WJ + jb);
        float4 wb = *(const float4*)(ws + d * WJ + jb + 4);
        float xr[4] = {xv.x, xv.y, xv.z, xv.w};
        float wr[8] = {wa.x, wa.y, wa.z, wa.w, wb.x, wb.y, wb.z, wb.w};
#pragma unroll
        for (int i = 0; i < 4; ++i)
#pragma unroll
            for (int jj = 0; jj < 8; ++jj)
                acc[i][jj] += xr[i] * wr[jj];
    }
}

__device__ __forceinline__ void store_tile(float* dst, int n0, int tn, int tj,
                                           float acc[4][8]) {
    int jb = tj * 8;
#pragma unroll
    for (int i = 0; i < 4; ++i) {
        int n = n0 + tn * 4 + i;
        if (n < N_NODES) {
            float4* p = (float4*)(dst + n * EMBED + jb);
            p[0] = make_float4(acc[i][0], acc[i][1], acc[i][2], acc[i][3]);
            p[1] = make_float4(acc[i][4], acc[i][5], acc[i][6], acc[i][7]);
        }
    }
}

// ---------------- K1: Q/K/V projections (tiled) ---------------------------
__global__ __launch_bounds__(256, 2)
void qkv_kernel(const float* __restrict__ x,
                const float* __restrict__ Wq, const float* __restrict__ bq,
                const float* __restrict__ Wk, const float* __restrict__ bk,
                const float* __restrict__ Wv, const float* __restrict__ bv) {
    __shared__ float xs[EMBED * XN];
    __shared__ float ws[EMBED * WJ];
    int tid = threadIdx.x;
    int n0 = blockIdx.x * TILE_N;

#pragma unroll
    for (int r = 0; r < 8; ++r) {
        int idx = r * 256 + tid;
        int n  = idx >> 5;
        int d4 = idx & 31;
        float4 xv = (n0 + n < N_NODES)
                  ? ((const float4*)(x + (size_t)(n0 + n) * EMBED))[d4]
                  : make_float4(0.f, 0.f, 0.f, 0.f);
        int d = d4 * 4;
        xs[(d + 0) * XN + n] = xv.x;
        xs[(d + 1) * XN + n] = xv.y;
        xs[(d + 2) * XN + n] = xv.z;
        xs[(d + 3) * XN + n] = xv.w;
    }

    int tn = tid & 15;
    int tj = tid >> 4;
    float acc[4][8];

    load_w_T(ws, Wq, tid);
    __syncthreads();
    gemm_tile(xs, ws, tn, tj, acc, bq);
    __syncthreads();
    store_tile(g_Q, n0, tn, tj, acc);

    load_w_T(ws, Wk, tid);
    __syncthreads();
    gemm_tile(xs, ws, tn, tj, acc, bk);
    __syncthreads();
    store_tile(g_K, n0, tn, tj, acc);

    load_w_T(ws, Wv, tid);
    __syncthreads();
    gemm_tile(xs, ws, tn, tj, acc, bv);
    store_tile(g_V, n0, tn, tj, acc);
}

// ---------------- K2: per-node gather, software-pipelined ------------------
// One warp per dst node. lane = eg*8 + h : eg in [0,4) edge slot, h head.
// Softmax is shift-invariant; logits are O(8), so no max-subtraction needed.
// Stores NORMALIZED agg (divided by z in-warp).
__global__ __launch_bounds__(256)
void gather_kernel(const float* __restrict__ bias,
                   float* __restrict__ out_logits) {
    int warp = (blockIdx.x * blockDim.x + threadIdx.x) >> 5;
    if (warp >= N_NODES) return;
    int lane = threadIdx.x & 31;
    int h  = lane & 7;
    int eg = lane >> 3;
    int n = warp;

    const float4* qp = (const float4*)(g_Q + n * EMBED + h * DKH);
    float4 q0 = qp[0], q1 = qp[1], q2 = qp[2], q3 = qp[3];

    float accv[16];
#pragma unroll
    for (int j = 0; j < 16; ++j) accv[j] = 0.0f;
    float accz = 0.0f;

    int cnt  = g_cnt[n];
    int base = g_start[n];

    // software pipeline: index + bias prefetched one iteration ahead
    int i = eg;
    int2 cur = make_int2(0, 0);
    float bcur = 0.0f;
    if (i < cnt) {
        cur  = g_sedge[base + i];
        bcur = bias[cur.x * NHEADS + h];
    }
    while (i < cnt) {
        int2 nxt; float bnxt = 0.0f;
        int i2 = i + 4;
        if (i2 < cnt) {
            nxt  = g_sedge[base + i2];
            bnxt = bias[nxt.x * NHEADS + h];
        }

        int eid = cur.x;
        int src = cur.y;
        const float4* kp = (const float4*)(g_K + src * EMBED + h * DKH);
        float4 k0 = kp[0], k1 = kp[1], k2 = kp[2], k3 = kp[3];
        const float4* vp = (const float4*)(g_V + src * EMBED + h * DKH);
        float4 v0 = vp[0], v1 = vp[1], v2 = vp[2], v3 = vp[3];

        float dot = q0.x*k0.x + q0.y*k0.y + q0.z*k0.z + q0.w*k0.w
                  + q1.x*k1.x + q1.y*k1.y + q1.z*k1.z + q1.w*k1.w
                  + q2.x*k2.x + q2.y*k2.y + q2.z*k2.z + q2.w*k2.w
                  + q3.x*k3.x + q3.y*k3.y + q3.z*k3.z + q3.w*k3.w;
        float logit = 0.25f * dot + bcur;          // scale = 1/sqrt(16)
        out_logits[eid * NHEADS + h] = logit;

        float ev = __expf(logit);
        accz += ev;
        accv[0]  += ev * v0.x;  accv[1]  += ev * v0.y;
        accv[2]  += ev * v0.z;  accv[3]  += ev * v0.w;
        accv[4]  += ev * v1.x;  accv[5]  += ev * v1.y;
        accv[6]  += ev * v1.z;  accv[7]  += ev * v1.w;
        accv[8]  += ev * v2.x;  accv[9]  += ev * v2.y;
        accv[10] += ev * v2.z;  accv[11] += ev * v2.w;
        accv[12] += ev * v3.x;  accv[13] += ev * v3.y;
        accv[14] += ev * v3.z;  accv[15] += ev * v3.w;

        cur = nxt; bcur = bnxt;
        i = i2;
    }

    // reduce over the 4 edge-slot lanes sharing each head (xor 8, 16)
    accz += __shfl_xor_sync(0xffffffffu, accz, 8);
    accz += __shfl_xor_sync(0xffffffffu, accz, 16);
#pragma unroll
    for (int j = 0; j < 16; ++j) {
        accv[j] += __shfl_xor_sync(0xffffffffu, accv[j], 8);
        accv[j] += __shfl_xor_sync(0xffffffffu, accv[j], 16);
    }

    float inv = (accz > 0.0f) ? (1.0f / accz) : 0.0f;
    float4 w = make_float4(accv[eg * 4 + 0] * inv, accv[eg * 4 + 1] * inv,
                           accv[eg * 4 + 2] * inv, accv[eg * 4 + 3] * inv);
    *(float4*)(g_agg + n * EMBED + h * DKH + eg * 4) = w;
}

// ---------------- K3: output projection (tiled; agg pre-normalized) -------
__global__ __launch_bounds__(256, 2)
void out_kernel(const float* __restrict__ Wo,
                const float* __restrict__ bo,
                float* __restrict__ out) {
    __shared__ float xs[EMBED * XN];
    __shared__ float ws[EMBED * WJ];
    int tid = threadIdx.x;
    int n0 = blockIdx.x * TILE_N;

#pragma unroll
    for (int r = 0; r < 8; ++r) {
        int idx = r * 256 + tid;
        int n  = idx >> 5;
        int d4 = idx & 31;
        float4 xv = (n0 + n < N_NODES)
                  ? ((const float4*)(g_agg + (size_t)(n0 + n) * EMBED))[d4]
                  : make_float4(0.f, 0.f, 0.f, 0.f);
        int d = d4 * 4;
        xs[(d + 0) * XN + n] = xv.x;
        xs[(d + 1) * XN + n] = xv.y;
        xs[(d + 2) * XN + n] = xv.z;
        xs[(d + 3) * XN + n] = xv.w;
    }

    load_w_T(ws, Wo, tid);
    __syncthreads();

    int tn = tid & 15;
    int tj = tid >> 4;
    float acc[4][8];
    gemm_tile(xs, ws, tn, tj, acc, bo);
    store_tile(out, n0, tn, tj, acc);
}

// ---------------- launch --------------------------------------------------
extern "C" void kernel_launch(void* const* d_in, const int* in_sizes, int n_in,
                              void* d_out, int out_size) {
    const float* x    = (const float*)d_in[0];
    const int*   ei   = (const int*)d_in[1];
    const float* bias = (const float*)d_in[2];
    const float* Wq   = (const float*)d_in[3];
    const float* bq   = (const float*)d_in[4];
    const float* Wk   = (const float*)d_in[5];
    const float* bk   = (const float*)d_in[6];
    const float* Wv   = (const float*)d_in[7];
    const float* bv   = (const float*)d_in[8];
    const float* Wo   = (const float*)d_in[9];
    const float* bo   = (const float*)d_in[10];

    float* out        = (float*)d_out;                       // [N_NODES, 128]
    float* out_logits = (float*)d_out + N_NODES * EMBED;     // [E, H, 1]

    init_kernel<<<(N_NODES + 255) / 256, 256>>>();
    hist_kernel<<<(N_EDGES + 255) / 256, 256>>>(ei);
    scan_kernel<<<1, 1024>>>();
    scatter_kernel<<<(N_EDGES + 255) / 256, 256>>>(ei);

    int nblk = (N_NODES + TILE_N - 1) / TILE_N;
    qkv_kernel<<<nblk, 256>>>(x, Wq, bq, Wk, bk, Wv, bv);

    int nwarp_blocks = (N_NODES * 32 + 255) / 256;
    gather_kernel<<<nwarp_blocks, 256>>>(bias, out_logits);

    out_kernel<<<nblk, 256>>>(Wo, bo, out);
}

// round 6
// speedup vs baseline: 1.6118x; 1.5876x over previous
#include <cuda_runtime.h>
#include <math.h>
#include <stdint.h>

#define N_NODES 25000
#define N_EDGES 400000
#define EMBED   128
#define NHEADS  8
#define DKH     16

// ---------------- scratch (static device globals; no allocation) -----------
__device__ __align__(16) float g_Q[N_NODES * EMBED];
__device__ __align__(16) float g_K[N_NODES * EMBED];
__device__ __align__(16) float g_V[N_NODES * EMBED];
__device__ __align__(16) float g_agg[N_NODES * EMBED];   // normalized sum(e*v)/z
__device__ int   g_cnt[N_NODES];                         // edges per dst
__device__ int   g_start[N_NODES];                       // exclusive prefix
__device__ int   g_cur[N_NODES];                         // scatter cursor
__device__ __align__(8) int2 g_sedge[N_EDGES];           // (eid, src) sorted by dst

// ---------------- K0: init (counters only) --------------------------------
__global__ void init_kernel() {
    int i = blockIdx.x * blockDim.x + threadIdx.x;
    if (i < N_NODES) g_cnt[i] = 0;
}

// ---------------- sort by dst: hist -> scan -> scatter ---------------------
__global__ void hist_kernel(const int* __restrict__ ei) {
    int e = blockIdx.x * blockDim.x + threadIdx.x;
    if (e < N_EDGES) atomicAdd(&g_cnt[ei[e]], 1);
}

__global__ void scan_kernel() {   // single block, 1024 threads
    __shared__ int s[1024];
    int t = threadIdx.x;
    const int CH = (N_NODES + 1023) / 1024;   // 25
    int b0 = t * CH;
    int sum = 0;
    for (int i = 0; i < CH; ++i) {
        int idx = b0 + i;
        if (idx < N_NODES) sum += g_cnt[idx];
    }
    s[t] = sum;
    __syncthreads();
    for (int off = 1; off < 1024; off <<= 1) {
        int v = (t >= off) ? s[t - off] : 0;
        __syncthreads();
        s[t] += v;
        __syncthreads();
    }
    int excl = (t == 0) ? 0 : s[t - 1];
    for (int i = 0; i < CH; ++i) {
        int idx = b0 + i;
        if (idx < N_NODES) {
            g_start[idx] = excl;
            g_cur[idx]   = excl;
            excl += g_cnt[idx];
        }
    }
}

__global__ void scatter_kernel(const int* __restrict__ ei) {
    int e = blockIdx.x * blockDim.x + threadIdx.x;
    if (e < N_EDGES) {
        int dst = ei[e];
        int src = ei[N_EDGES + e];
        int pos = atomicAdd(&g_cur[dst], 1);
        g_sedge[pos] = make_int2(e, src);
    }
}

// ================= tf32 tensor-core GEMM: Out = X @ W^T + b ================
// X [nrows,128] row-major, W [128,128] row-major, Out [nrows,128].
// mma.m16n8k8.row.col: B col-major (k fastest) == W's native [j][k] layout,
// so no transpose is ever materialized. Smem staged in natural layout with
// XOR swizzle on the k index: elem (row, k) lives at [row*32 + (k ^ ((row&7)<<2))]
// within a 32-wide K-chunk -> conflict-free float4 fills AND fragment loads.

#define GM_BLK 128
#define GKC    32

__device__ __forceinline__ float to_tf32(float x) {
    float r;
    asm("cvt.rna.tf32.f32 %0, %1;" : "=f"(r) : "f"(x));
    return r;
}

__device__ __forceinline__ void mma_tf32(float c[4], const unsigned a[4], const unsigned b[2]) {
    asm volatile(
        "mma.sync.aligned.m16n8k8.row.col.f32.tf32.tf32.f32 "
        "{%0,%1,%2,%3}, {%4,%5,%6,%7}, {%8,%9}, {%0,%1,%2,%3};\n"
        : "+f"(c[0]), "+f"(c[1]), "+f"(c[2]), "+f"(c[3])
        : "r"(a[0]), "r"(a[1]), "r"(a[2]), "r"(a[3]), "r"(b[0]), "r"(b[1]));
}

__global__ __launch_bounds__(256)
void gemm_tf32_kernel(const float* __restrict__ X,
                      const float* __restrict__ W,
                      const float* __restrict__ bias,
                      float* __restrict__ Out,
                      int nrows) {
    __shared__ float xs[GM_BLK * GKC];   // [n][kl] swizzled
    __shared__ float ws[EMBED * GKC];    // [j][kl] swizzled
    int tid  = threadIdx.x;
    int lane = tid & 31;
    int w    = tid >> 5;
    int n0   = blockIdx.x * GM_BLK;

    int mq = w & 3;    // rows 32*mq .. +31 (two 16-row subtiles)
    int nh = w >> 2;   // cols 64*nh .. +63 (eight 8-col subtiles)

    float c[2][8][4];
#pragma unroll
    for (int mi = 0; mi < 2; ++mi)
#pragma unroll
        for (int ni = 0; ni < 8; ++ni)
#pragma unroll
            for (int q = 0; q < 4; ++q) c[mi][ni][q] = 0.0f;

    for (int kc = 0; kc < EMBED; kc += GKC) {
        // stage X chunk: 128 rows x 32 k (1024 float4)
#pragma unroll
        for (int r = 0; r < 4; ++r) {
            int idx = r * 256 + tid;
            int n  = idx >> 3;
            int k4 = idx & 7;
            float4 v = make_float4(0.f, 0.f, 0.f, 0.f);
            if (n0 + n < nrows)
                v = *(const float4*)(X + (size_t)(n0 + n) * EMBED + kc + 4 * k4);
            v.x = to_tf32(v.x); v.y = to_tf32(v.y);
            v.z = to_tf32(v.z); v.w = to_tf32(v.w);
            int ks = (4 * k4) ^ ((n & 7) << 2);
            *(float4*)(xs + n * GKC + ks) = v;
        }
        // stage W chunk: 128 j x 32 k (native layout, no transpose)
#pragma unroll
        for (int r = 0; r < 4; ++r) {
            int idx = r * 256 + tid;
            int j  = idx >> 3;
            int k4 = idx & 7;
            float4 v = *(const float4*)(W + (size_t)j * EMBED + kc + 4 * k4);
            v.x = to_tf32(v.x); v.y = to_tf32(v.y);
            v.z = to_tf32(v.z); v.w = to_tf32(v.w);
            int ks = (4 * k4) ^ ((j & 7) << 2);
            *(float4*)(ws + j * GKC + ks) = v;
        }
        __syncthreads();

#pragma unroll
        for (int k0 = 0; k0 < GKC; k0 += 8) {
            unsigned a[2][4];
#pragma unroll
            for (int mi = 0; mi < 2; ++mi) {
                int rrow = mq * 32 + mi * 16 + (lane >> 2);
                int sw = (rrow & 7) << 2;
                int kA = k0 + (lane & 3);
                a[mi][0] = __float_as_uint(xs[rrow * GKC + (kA ^ sw)]);
                a[mi][1] = __float_as_uint(xs[(rrow + 8) * GKC + (kA ^ sw)]);
                a[mi][2] = __float_as_uint(xs[rrow * GKC + ((kA + 4) ^ sw)]);
                a[mi][3] = __float_as_uint(xs[(rrow + 8) * GKC + ((kA + 4) ^ sw)]);
            }
            unsigned b[8][2];
#pragma unroll
            for (int ni = 0; ni < 8; ++ni) {
                int j = nh * 64 + ni * 8 + (lane >> 2);
                int sw = (j & 7) << 2;
                int kB = k0 + (lane & 3);
                b[ni][0] = __float_as_uint(ws[j * GKC + (kB ^ sw)]);
                b[ni][1] = __float_as_uint(ws[j * GKC + ((kB + 4) ^ sw)]);
            }
#pragma unroll
            for (int mi = 0; mi < 2; ++mi)
#pragma unroll
                for (int ni = 0; ni < 8; ++ni)
                    mma_tf32(c[mi][ni], a[mi], b[ni]);
        }
        __syncthreads();
    }

    // epilogue: bias + store (float2 per fragment half)
#pragma unroll
    for (int mi = 0; mi < 2; ++mi) {
        int r = n0 + mq * 32 + mi * 16 + (lane >> 2);
#pragma unroll
        for (int ni = 0; ni < 8; ++ni) {
            int col = nh * 64 + ni * 8 + 2 * (lane & 3);
            float b0 = bias[col], b1 = bias[col + 1];
            if (r < nrows)
                *(float2*)(Out + (size_t)r * EMBED + col) =
                    make_float2(c[mi][ni][0] + b0, c[mi][ni][1] + b1);
            if (r + 8 < nrows)
                *(float2*)(Out + (size_t)(r + 8) * EMBED + col) =
                    make_float2(c[mi][ni][2] + b0, c[mi][ni][3] + b1);
        }
    }
}

// ---------------- gather: per-node softmax-accumulate (atomic-free) --------
// One warp per dst node. lane = eg*8 + h. Softmax is shift-invariant; logits
// are O(8), so no max-subtraction needed. Stores NORMALIZED agg.
__global__ __launch_bounds__(256)
void gather_kernel(const float* __restrict__ bias,
                   float* __restrict__ out_logits) {
    int warp = (blockIdx.x * blockDim.x + threadIdx.x) >> 5;
    if (warp >= N_NODES) return;
    int lane = threadIdx.x & 31;
    int h  = lane & 7;
    int eg = lane >> 3;
    int n = warp;

    const float4* qp = (const float4*)(g_Q + n * EMBED + h * DKH);
    float4 q0 = qp[0], q1 = qp[1], q2 = qp[2], q3 = qp[3];

    float accv[16];
#pragma unroll
    for (int j = 0; j < 16; ++j) accv[j] = 0.0f;
    float accz = 0.0f;

    int cnt  = g_cnt[n];
    int base = g_start[n];

    int i = eg;
    int2 cur = make_int2(0, 0);
    float bcur = 0.0f;
    if (i < cnt) {
        cur  = g_sedge[base + i];
        bcur = bias[cur.x * NHEADS + h];
    }
    while (i < cnt) {
        int2 nxt; float bnxt = 0.0f;
        int i2 = i + 4;
        if (i2 < cnt) {
            nxt  = g_sedge[base + i2];
            bnxt = bias[nxt.x * NHEADS + h];
        }

        int eid = cur.x;
        int src = cur.y;
        const float4* kp = (const float4*)(g_K + src * EMBED + h * DKH);
        float4 k0 = kp[0], k1 = kp[1], k2 = kp[2], k3 = kp[3];
        const float4* vp = (const float4*)(g_V + src * EMBED + h * DKH);
        float4 v0 = vp[0], v1 = vp[1], v2 = vp[2], v3 = vp[3];

        float dot = q0.x*k0.x + q0.y*k0.y + q0.z*k0.z + q0.w*k0.w
                  + q1.x*k1.x + q1.y*k1.y + q1.z*k1.z + q1.w*k1.w
                  + q2.x*k2.x + q2.y*k2.y + q2.z*k2.z + q2.w*k2.w
                  + q3.x*k3.x + q3.y*k3.y + q3.z*k3.z + q3.w*k3.w;
        float logit = 0.25f * dot + bcur;          // scale = 1/sqrt(16)
        out_logits[eid * NHEADS + h] = logit;

        float ev = __expf(logit);
        accz += ev;
        accv[0]  += ev * v0.x;  accv[1]  += ev * v0.y;
        accv[2]  += ev * v0.z;  accv[3]  += ev * v0.w;
        accv[4]  += ev * v1.x;  accv[5]  += ev * v1.y;
        accv[6]  += ev * v1.z;  accv[7]  += ev * v1.w;
        accv[8]  += ev * v2.x;  accv[9]  += ev * v2.y;
        accv[10] += ev * v2.z;  accv[11] += ev * v2.w;
        accv[12] += ev * v3.x;  accv[13] += ev * v3.y;
        accv[14] += ev * v3.z;  accv[15] += ev * v3.w;

        cur = nxt; bcur = bnxt;
        i = i2;
    }

    accz += __shfl_xor_sync(0xffffffffu, accz, 8);
    accz += __shfl_xor_sync(0xffffffffu, accz, 16);
#pragma unroll
    for (int j = 0; j < 16; ++j) {
        accv[j] += __shfl_xor_sync(0xffffffffu, accv[j], 8);
        accv[j] += __shfl_xor_sync(0xffffffffu, accv[j], 16);
    }

    float inv = (accz > 0.0f) ? (1.0f / accz) : 0.0f;
    float4 wv = make_float4(accv[eg * 4 + 0] * inv, accv[eg * 4 + 1] * inv,
                            accv[eg * 4 + 2] * inv, accv[eg * 4 + 3] * inv);
    *(float4*)(g_agg + n * EMBED + h * DKH + eg * 4) = wv;
}

// ---------------- launch --------------------------------------------------
extern "C" void kernel_launch(void* const* d_in, const int* in_sizes, int n_in,
                              void* d_out, int out_size) {
    const float* x    = (const float*)d_in[0];
    const int*   ei   = (const int*)d_in[1];
    const float* bias = (const float*)d_in[2];
    const float* Wq   = (const float*)d_in[3];
    const float* bq   = (const float*)d_in[4];
    const float* Wk   = (const float*)d_in[5];
    const float* bk   = (const float*)d_in[6];
    const float* Wv   = (const float*)d_in[7];
    const float* bv   = (const float*)d_in[8];
    const float* Wo   = (const float*)d_in[9];
    const float* bo   = (const float*)d_in[10];

    float* out        = (float*)d_out;                       // [N_NODES, 128]
    float* out_logits = (float*)d_out + N_NODES * EMBED;     // [E, H, 1]

    init_kernel<<<(N_NODES + 255) / 256, 256>>>();
    hist_kernel<<<(N_EDGES + 255) / 256, 256>>>(ei);
    scan_kernel<<<1, 1024>>>();
    scatter_kernel<<<(N_EDGES + 255) / 256, 256>>>(ei);

    float* gQ; cudaGetSymbolAddress((void**)&gQ, g_Q);
    float* gK; cudaGetSymbolAddress((void**)&gK, g_K);
    float* gV; cudaGetSymbolAddress((void**)&gV, g_V);
    float* gA; cudaGetSymbolAddress((void**)&gA, g_agg);

    int gblk = (N_NODES + GM_BLK - 1) / GM_BLK;
    gemm_tf32_kernel<<<gblk, 256>>>(x, Wq, bq, gQ, N_NODES);
    gemm_tf32_kernel<<<gblk, 256>>>(x, Wk, bk, gK, N_NODES);
    gemm_tf32_kernel<<<gblk, 256>>>(x, Wv, bv, gV, N_NODES);

    int nwarp_blocks = (N_NODES * 32 + 255) / 256;
    gather_kernel<<<nwarp_blocks, 256>>>(bias, out_logits);

    gemm_tf32_kernel<<<gblk, 256>>>(gA, Wo, bo, out, N_NODES);
}